// round 1
// baseline (speedup 1.0000x reference)
#include <cuda_runtime.h>
#include <cuda_bf16.h>

// Problem shapes (fixed by the reference)
#define BB   4
#define SS   2048
#define DIN  4096
#define DOUT 4096
#define CAP  1024
#define MTOT (BB * SS)   // 8192

// GEMM tiling
#define BM 128
#define BN 128
#define BK 16
#define NTHREADS 256

// Scratch for the associative-memory path (allocation-free rule: __device__ globals)
__device__ float g_scores[CAP];
__device__ float g_attn[CAP];
__device__ float g_mem_out[DOUT];

// ---------------------------------------------------------------------------
// Kernel 1: scores[c] = mem_keys[c,:] . q,  q = x[0,0,:]
// ---------------------------------------------------------------------------
__global__ void scores_kernel(const float* __restrict__ keys,
                              const float* __restrict__ x) {
    const int c = blockIdx.x;
    const float4* row = reinterpret_cast<const float4*>(keys + (size_t)c * DIN);
    const float4* q   = reinterpret_cast<const float4*>(x);
    float sum = 0.f;
    for (int i = threadIdx.x; i < DIN / 4; i += NTHREADS) {
        float4 a = row[i], b = q[i];
        sum += a.x * b.x + a.y * b.y + a.z * b.z + a.w * b.w;
    }
    // warp reduce
    #pragma unroll
    for (int off = 16; off; off >>= 1)
        sum += __shfl_down_sync(0xffffffffu, sum, off);
    __shared__ float red[NTHREADS / 32];
    if ((threadIdx.x & 31) == 0) red[threadIdx.x >> 5] = sum;
    __syncthreads();
    if (threadIdx.x < (NTHREADS / 32)) {
        float v = red[threadIdx.x];
        #pragma unroll
        for (int off = NTHREADS / 64; off; off >>= 1)
            v += __shfl_down_sync(0xffu, v, off);
        if (threadIdx.x == 0) g_scores[c] = v;
    }
}

// ---------------------------------------------------------------------------
// Kernel 2: attn = softmax(scores), single block of CAP threads
// ---------------------------------------------------------------------------
__global__ void softmax_kernel() {
    const int t = threadIdx.x;
    float v = g_scores[t];
    __shared__ float red[32];
    // block max
    float m = v;
    #pragma unroll
    for (int off = 16; off; off >>= 1)
        m = fmaxf(m, __shfl_xor_sync(0xffffffffu, m, off));
    if ((t & 31) == 0) red[t >> 5] = m;
    __syncthreads();
    if (t < 32) {
        float w = red[t];
        #pragma unroll
        for (int off = 16; off; off >>= 1)
            w = fmaxf(w, __shfl_xor_sync(0xffffffffu, w, off));
        red[0] = w;
    }
    __syncthreads();
    m = red[0];
    __syncthreads();           // red reused below
    float e = expf(v - m);
    // block sum
    float s = e;
    #pragma unroll
    for (int off = 16; off; off >>= 1)
        s += __shfl_xor_sync(0xffffffffu, s, off);
    if ((t & 31) == 0) red[t >> 5] = s;
    __syncthreads();
    if (t < 32) {
        float w = red[t];
        #pragma unroll
        for (int off = 16; off; off >>= 1)
            w += __shfl_xor_sync(0xffffffffu, w, off);
        red[0] = w;
    }
    __syncthreads();
    g_attn[t] = e / red[0];
}

// ---------------------------------------------------------------------------
// Kernel 3: mem_out[o] = attn . mem_values[:, o]
// ---------------------------------------------------------------------------
__global__ void memout_kernel(const float* __restrict__ vals) {
    const int o = blockIdx.x * blockDim.x + threadIdx.x;
    float acc = 0.f;
    #pragma unroll 4
    for (int c = 0; c < CAP; c++)
        acc = fmaf(g_attn[c], vals[(size_t)c * DOUT + o], acc);
    g_mem_out[o] = acc;
}

// ---------------------------------------------------------------------------
// Kernel 4: main GEMM  C[m,o] = scale[o] * (x[m,:] . Wlat[o,:]) + 0.01*mem_out[o]
// A: [MTOT, DIN] row-major, Bw: [DOUT, DIN] row-major (NT GEMM, both K-contiguous)
// 128x128x16 tiles, 256 threads, 8x8 microtile, double-buffered smem.
// ---------------------------------------------------------------------------
__global__ __launch_bounds__(NTHREADS, 2)
void gemm_kernel(const float* __restrict__ A,
                 const float* __restrict__ Bw,
                 const float* __restrict__ scales,
                 float* __restrict__ C) {
    __shared__ float As[2][BK][BM];
    __shared__ float Bs[2][BK][BN];

    const int tid = threadIdx.x;
    const int tx = tid & 15;       // 0..15 -> N direction
    const int ty = tid >> 4;       // 0..15 -> M direction
    const int block_m = blockIdx.y * BM;
    const int block_n = blockIdx.x * BN;

    // Global-load mapping: 512 float4 per 128x16 tile, 2 per thread.
    // f = tid + 256*r : row = f>>2, k-quad = (f&3)*4
    float4 a_reg[2], b_reg[2];

    const int row0 = (tid) >> 2;
    const int kq0  = ((tid) & 3) << 2;
    const int row1 = (tid + 256) >> 2;
    const int kq1  = ((tid + 256) & 3) << 2;

    const float* Aptr0 = A  + (size_t)(block_m + row0) * DIN + kq0;
    const float* Aptr1 = A  + (size_t)(block_m + row1) * DIN + kq1;
    const float* Bptr0 = Bw + (size_t)(block_n + row0) * DIN + kq0;
    const float* Bptr1 = Bw + (size_t)(block_n + row1) * DIN + kq1;

    float acc[8][8];
    #pragma unroll
    for (int i = 0; i < 8; i++)
        #pragma unroll
        for (int j = 0; j < 8; j++) acc[i][j] = 0.f;

    // Preload tile 0
    a_reg[0] = *reinterpret_cast<const float4*>(Aptr0);
    a_reg[1] = *reinterpret_cast<const float4*>(Aptr1);
    b_reg[0] = *reinterpret_cast<const float4*>(Bptr0);
    b_reg[1] = *reinterpret_cast<const float4*>(Bptr1);
    {
        const float* ar = reinterpret_cast<const float*>(&a_reg[0]);
        const float* br = reinterpret_cast<const float*>(&b_reg[0]);
        #pragma unroll
        for (int j = 0; j < 4; j++) { As[0][kq0 + j][row0] = ar[j];     Bs[0][kq0 + j][row0] = br[j]; }
        ar = reinterpret_cast<const float*>(&a_reg[1]);
        br = reinterpret_cast<const float*>(&b_reg[1]);
        #pragma unroll
        for (int j = 0; j < 4; j++) { As[0][kq1 + j][row1] = ar[j];     Bs[0][kq1 + j][row1] = br[j]; }
    }
    __syncthreads();

    const int nk = DIN / BK;    // 256
    for (int kt = 0; kt < nk; kt++) {
        const int buf = kt & 1;
        const bool has_next = (kt + 1 < nk);
        if (has_next) {
            const int koff = (kt + 1) * BK;
            a_reg[0] = *reinterpret_cast<const float4*>(Aptr0 + koff);
            a_reg[1] = *reinterpret_cast<const float4*>(Aptr1 + koff);
            b_reg[0] = *reinterpret_cast<const float4*>(Bptr0 + koff);
            b_reg[1] = *reinterpret_cast<const float4*>(Bptr1 + koff);
        }

        #pragma unroll
        for (int k = 0; k < BK; k++) {
            float4 a0 = *reinterpret_cast<const float4*>(&As[buf][k][ty * 8]);
            float4 a1 = *reinterpret_cast<const float4*>(&As[buf][k][ty * 8 + 4]);
            float4 b0 = *reinterpret_cast<const float4*>(&Bs[buf][k][tx * 8]);
            float4 b1 = *reinterpret_cast<const float4*>(&Bs[buf][k][tx * 8 + 4]);
            float av[8] = {a0.x, a0.y, a0.z, a0.w, a1.x, a1.y, a1.z, a1.w};
            float bv[8] = {b0.x, b0.y, b0.z, b0.w, b1.x, b1.y, b1.z, b1.w};
            #pragma unroll
            for (int i = 0; i < 8; i++)
                #pragma unroll
                for (int j = 0; j < 8; j++)
                    acc[i][j] = fmaf(av[i], bv[j], acc[i][j]);
        }

        if (has_next) {
            const int nb = buf ^ 1;
            const float* ar = reinterpret_cast<const float*>(&a_reg[0]);
            const float* br = reinterpret_cast<const float*>(&b_reg[0]);
            #pragma unroll
            for (int j = 0; j < 4; j++) { As[nb][kq0 + j][row0] = ar[j];  Bs[nb][kq0 + j][row0] = br[j]; }
            ar = reinterpret_cast<const float*>(&a_reg[1]);
            br = reinterpret_cast<const float*>(&b_reg[1]);
            #pragma unroll
            for (int j = 0; j < 4; j++) { As[nb][kq1 + j][row1] = ar[j];  Bs[nb][kq1 + j][row1] = br[j]; }
        }
        __syncthreads();
    }

    // Epilogue: per-column scale + memory bias
    float sc[8], mo[8];
    #pragma unroll
    for (int j = 0; j < 8; j++) {
        const int n = block_n + tx * 8 + j;
        sc[j] = scales[n];
        mo[j] = 0.01f * g_mem_out[n];
    }
    #pragma unroll
    for (int i = 0; i < 8; i++) {
        const size_t crow = (size_t)(block_m + ty * 8 + i) * DOUT + block_n + tx * 8;
        float4 o0, o1;
        o0.x = fmaf(acc[i][0], sc[0], mo[0]);
        o0.y = fmaf(acc[i][1], sc[1], mo[1]);
        o0.z = fmaf(acc[i][2], sc[2], mo[2]);
        o0.w = fmaf(acc[i][3], sc[3], mo[3]);
        o1.x = fmaf(acc[i][4], sc[4], mo[4]);
        o1.y = fmaf(acc[i][5], sc[5], mo[5]);
        o1.z = fmaf(acc[i][6], sc[6], mo[6]);
        o1.w = fmaf(acc[i][7], sc[7], mo[7]);
        *reinterpret_cast<float4*>(C + crow)     = o0;
        *reinterpret_cast<float4*>(C + crow + 4) = o1;
    }
}

// ---------------------------------------------------------------------------
// Launch
// ---------------------------------------------------------------------------
extern "C" void kernel_launch(void* const* d_in, const int* in_sizes, int n_in,
                              void* d_out, int out_size) {
    const float* x      = (const float*)d_in[0];  // [B,S,DIN]
    const float* wlat   = (const float*)d_in[1];  // [DOUT,DIN]
    const float* wscale = (const float*)d_in[2];  // [DOUT,1]
    const float* mkeys  = (const float*)d_in[3];  // [CAP,DIN]
    const float* mvals  = (const float*)d_in[4];  // [CAP,DOUT]
    float* out = (float*)d_out;                   // [B,S,DOUT]

    (void)in_sizes; (void)n_in; (void)out_size;

    // Associative memory path (tiny)
    scores_kernel<<<CAP, NTHREADS>>>(mkeys, x);
    softmax_kernel<<<1, CAP>>>();
    memout_kernel<<<DOUT / NTHREADS, NTHREADS>>>(mvals);

    // Main GEMM with fused scale + memory bias epilogue
    dim3 grid(DOUT / BN, MTOT / BM);   // 32 x 64
    gemm_kernel<<<grid, NTHREADS>>>(x, wlat, wscale, out);
}

// round 4
// speedup vs baseline: 2.5282x; 2.5282x over previous
#include <cuda_runtime.h>
#include <cuda_bf16.h>
#include <cstdint>

// ---------------------------------------------------------------- shapes
#define BB   4
#define SS   2048
#define DIN  4096
#define DOUT 4096
#define CAP  1024
#define MTOT (BB * SS)       // 8192

// GEMM tiling
#define BM 128
#define BN 256
#define BK 32                 // bf16 elems per stage chunk
#define NCHUNK (DIN / BK)     // 128
#define STAGES 3
#define NTHREADS 256

// smem geometry: rows padded 32 -> 40 bf16 (80B pitch, conflict-free ldmatrix)
#define ROWP 40
#define A_BUF_B (BM * ROWP * 2)     // 10240
#define B_BUF_B (BN * ROWP * 2)     // 20480
#define STAGE_B (2 * A_BUF_B + 2 * B_BUF_B)   // 61440
#define SM_STAGE0 2048
#define GEMM_SMEM (SM_STAGE0 + STAGES * STAGE_B)   // 186368

// ---------------------------------------------------------------- scratch
__device__ float g_scores[CAP];
__device__ float g_attn[CAP];
__device__ float g_mem_out[DOUT];
__device__ __align__(1024) __nv_bfloat16 g_xhi[(size_t)MTOT * DIN];
__device__ __align__(1024) __nv_bfloat16 g_xlo[(size_t)MTOT * DIN];
__device__ __align__(1024) __nv_bfloat16 g_whi[(size_t)DOUT * DIN];
__device__ __align__(1024) __nv_bfloat16 g_wlo[(size_t)DOUT * DIN];

// ---------------------------------------------------------------- PTX helpers
__device__ __forceinline__ uint32_t smem_to_u32(const void* p) {
    uint32_t a;
    asm("{ .reg .u64 t; cvta.to.shared.u64 t, %1; cvt.u32.u64 %0, t; }" : "=r"(a) : "l"(p));
    return a;
}
__device__ __forceinline__ void cp16(uint32_t dst, const void* src) {
    asm volatile("cp.async.cg.shared.global [%0], [%1], 16;" :: "r"(dst), "l"(src));
}
#define CP_COMMIT() asm volatile("cp.async.commit_group;" ::: "memory")
#define CP_WAIT(n)  asm volatile("cp.async.wait_group %0;" :: "n"(n) : "memory")

__device__ __forceinline__ void ldsm_x4(uint32_t* r, uint32_t addr) {
    asm volatile("ldmatrix.sync.aligned.m8n8.x4.shared.b16 {%0,%1,%2,%3}, [%4];"
        : "=r"(r[0]), "=r"(r[1]), "=r"(r[2]), "=r"(r[3]) : "r"(addr));
}
__device__ __forceinline__ void mma16816(float* c, const uint32_t* a, const uint32_t* b) {
    asm volatile("mma.sync.aligned.m16n8k16.row.col.f32.bf16.bf16.f32 "
        "{%0,%1,%2,%3}, {%4,%5,%6,%7}, {%8,%9}, {%0,%1,%2,%3};"
        : "+f"(c[0]), "+f"(c[1]), "+f"(c[2]), "+f"(c[3])
        : "r"(a[0]), "r"(a[1]), "r"(a[2]), "r"(a[3]), "r"(b[0]), "r"(b[1]));
}

// ---------------------------------------------------------------- small kernels
__global__ void scores_kernel(const float* __restrict__ keys, const float* __restrict__ x) {
    const int c = blockIdx.x;
    const float4* row = reinterpret_cast<const float4*>(keys + (size_t)c * DIN);
    const float4* q   = reinterpret_cast<const float4*>(x);
    float sum = 0.f;
    for (int i = threadIdx.x; i < DIN / 4; i += NTHREADS) {
        float4 a = row[i], b = q[i];
        sum += a.x * b.x + a.y * b.y + a.z * b.z + a.w * b.w;
    }
    #pragma unroll
    for (int off = 16; off; off >>= 1) sum += __shfl_down_sync(0xffffffffu, sum, off);
    __shared__ float red[NTHREADS / 32];
    if ((threadIdx.x & 31) == 0) red[threadIdx.x >> 5] = sum;
    __syncthreads();
    if (threadIdx.x < (NTHREADS / 32)) {
        float v = red[threadIdx.x];
        #pragma unroll
        for (int off = NTHREADS / 64; off; off >>= 1) v += __shfl_down_sync(0xffu, v, off);
        if (threadIdx.x == 0) g_scores[c] = v;
    }
}

__global__ void softmax_kernel() {
    const int t = threadIdx.x;
    float v = g_scores[t];
    __shared__ float red[32];
    float m = v;
    #pragma unroll
    for (int off = 16; off; off >>= 1) m = fmaxf(m, __shfl_xor_sync(0xffffffffu, m, off));
    if ((t & 31) == 0) red[t >> 5] = m;
    __syncthreads();
    if (t < 32) {
        float w = red[t];
        #pragma unroll
        for (int off = 16; off; off >>= 1) w = fmaxf(w, __shfl_xor_sync(0xffffffffu, w, off));
        red[0] = w;
    }
    __syncthreads();
    m = red[0];
    __syncthreads();
    float e = expf(v - m);
    float s = e;
    #pragma unroll
    for (int off = 16; off; off >>= 1) s += __shfl_xor_sync(0xffffffffu, s, off);
    if ((t & 31) == 0) red[t >> 5] = s;
    __syncthreads();
    if (t < 32) {
        float w = red[t];
        #pragma unroll
        for (int off = 16; off; off >>= 1) w += __shfl_xor_sync(0xffffffffu, w, off);
        red[0] = w;
    }
    __syncthreads();
    g_attn[t] = e / red[0];
}

__global__ void memout_kernel(const float* __restrict__ vals) {
    const int o = blockIdx.x * blockDim.x + threadIdx.x;
    float acc = 0.f;
    #pragma unroll 4
    for (int c = 0; c < CAP; c++) acc = fmaf(g_attn[c], vals[(size_t)c * DOUT + o], acc);
    g_mem_out[o] = acc;
}

// split fp32 -> bf16 hi + bf16 lo (residual)
__global__ void convert_split_kernel(const float* __restrict__ src,
                                     __nv_bfloat16* __restrict__ hi,
                                     __nv_bfloat16* __restrict__ lo, int n4) {
    int i = blockIdx.x * blockDim.x + threadIdx.x;
    if (i >= n4) return;
    float4 v = reinterpret_cast<const float4*>(src)[i];
    float vv[4] = {v.x, v.y, v.z, v.w};
    __nv_bfloat16 h[4], l[4];
    #pragma unroll
    for (int j = 0; j < 4; j++) {
        h[j] = __float2bfloat16(vv[j]);
        l[j] = __float2bfloat16(vv[j] - __bfloat162float(h[j]));
    }
    __nv_bfloat162 h01, h23, l01, l23;
    h01.x = h[0]; h01.y = h[1]; h23.x = h[2]; h23.y = h[3];
    l01.x = l[0]; l01.y = l[1]; l23.x = l[2]; l23.y = l[3];
    reinterpret_cast<__nv_bfloat162*>(hi)[i * 2 + 0] = h01;
    reinterpret_cast<__nv_bfloat162*>(hi)[i * 2 + 1] = h23;
    reinterpret_cast<__nv_bfloat162*>(lo)[i * 2 + 0] = l01;
    reinterpret_cast<__nv_bfloat162*>(lo)[i * 2 + 1] = l23;
}

// ---------------------------------------------------------------- main GEMM
// C[m,n] = scale[n] * (Xhi+Xlo)[m,:].(Whi+Wlo)[n,:] + 0.01*mem_out[n]
// (lo*lo term dropped: O(2^-18) relative)
__global__ __launch_bounds__(NTHREADS, 1)
void gemm_mma_kernel(const float* __restrict__ scales, float* __restrict__ C) {
    extern __shared__ char smem[];
    const uint32_t smem_u32 = smem_to_u32(smem);
    float* s_scale = reinterpret_cast<float*>(smem);
    float* s_memo  = reinterpret_cast<float*>(smem + 1024);

    const int tid  = threadIdx.x;
    const int wid  = tid >> 5;
    const int lane = tid & 31;
    const int warp_m = wid & 3;        // 4 strips of 32 rows
    const int warp_n = wid >> 2;       // 2 strips of 128 cols
    const int block_m = blockIdx.y * BM;
    const int block_n = blockIdx.x * BN;

    // epilogue vectors
    for (int i = tid; i < BN; i += NTHREADS) {
        s_scale[i] = scales[block_n + i];
        s_memo[i]  = 0.01f * g_mem_out[block_n + i];
    }

    // global load base indices (per thread): chunk j covers 16B
    // A: idx = tid + 256*j (j=0..1): row = idx>>2 (0..127), c = idx&3
    // B: idx = tid + 256*j (j=0..3): row = idx>>2 (0..255), c = idx&3
    const __nv_bfloat16* gXhi = g_xhi + (size_t)block_m * DIN;
    const __nv_bfloat16* gXlo = g_xlo + (size_t)block_m * DIN;
    const __nv_bfloat16* gWhi = g_whi + (size_t)block_n * DIN;
    const __nv_bfloat16* gWlo = g_wlo + (size_t)block_n * DIN;

    auto load_stage = [&](int kt, int s) {
        const int k0 = kt * BK;
        const uint32_t st = smem_u32 + SM_STAGE0 + s * STAGE_B;
        const uint32_t sAhi = st;
        const uint32_t sAlo = st + A_BUF_B;
        const uint32_t sBhi = st + 2 * A_BUF_B;
        const uint32_t sBlo = st + 2 * A_BUF_B + B_BUF_B;
        #pragma unroll
        for (int j = 0; j < 2; j++) {
            int idx = tid + NTHREADS * j;
            int row = idx >> 2, c = idx & 3;
            size_t go = (size_t)row * DIN + k0 + c * 8;
            uint32_t so = row * (ROWP * 2) + c * 16;
            cp16(sAhi + so, gXhi + go);
            cp16(sAlo + so, gXlo + go);
        }
        #pragma unroll
        for (int j = 0; j < 4; j++) {
            int idx = tid + NTHREADS * j;
            int row = idx >> 2, c = idx & 3;
            size_t go = (size_t)row * DIN + k0 + c * 8;
            uint32_t so = row * (ROWP * 2) + c * 16;
            cp16(sBhi + so, gWhi + go);
            cp16(sBlo + so, gWlo + go);
        }
        CP_COMMIT();
    };

    float acc[2][16][4];
    #pragma unroll
    for (int i = 0; i < 2; i++)
        #pragma unroll
        for (int t = 0; t < 16; t++)
            #pragma unroll
            for (int r = 0; r < 4; r++) acc[i][t][r] = 0.f;

    // ldmatrix lane address components
    const int a_row = lane & 15;                      // rows 0-15
    const int a_k   = (lane >> 4) * 8;                // k half
    const int b_row = (lane & 7) + ((lane >> 4) << 3);// n row within 16
    const int b_k   = ((lane >> 3) & 1) * 8;          // k half

    // prologue
    load_stage(0, 0);
    load_stage(1, 1);

    for (int kt = 0; kt < NCHUNK; kt++) {
        if (kt + 1 < NCHUNK) { CP_WAIT(1); } else { CP_WAIT(0); }
        __syncthreads();
        if (kt + 2 < NCHUNK) load_stage(kt + 2, (kt + 2) % STAGES);

        const uint32_t st = smem_u32 + SM_STAGE0 + (kt % STAGES) * STAGE_B;
        const uint32_t sAhi = st;
        const uint32_t sAlo = st + A_BUF_B;
        const uint32_t sBhi = st + 2 * A_BUF_B;
        const uint32_t sBlo = st + 2 * A_BUF_B + B_BUF_B;

        #pragma unroll
        for (int kk = 0; kk < BK; kk += 16) {
            uint32_t ahi[2][4], alo[2][4];
            #pragma unroll
            for (int i = 0; i < 2; i++) {
                uint32_t off = (uint32_t)(warp_m * 32 + i * 16 + a_row) * (ROWP * 2)
                             + (kk + a_k) * 2;
                ldsm_x4(ahi[i], sAhi + off);
                ldsm_x4(alo[i], sAlo + off);
            }
            #pragma unroll
            for (int p = 0; p < 8; p++) {
                uint32_t boff = (uint32_t)(warp_n * 128 + p * 16 + b_row) * (ROWP * 2)
                              + (kk + b_k) * 2;
                uint32_t bh[4], bl[4];
                ldsm_x4(bh, sBhi + boff);
                ldsm_x4(bl, sBlo + boff);
                // hh
                mma16816(acc[0][2 * p],     ahi[0], bh);
                mma16816(acc[0][2 * p + 1], ahi[0], bh + 2);
                mma16816(acc[1][2 * p],     ahi[1], bh);
                mma16816(acc[1][2 * p + 1], ahi[1], bh + 2);
                // hl
                mma16816(acc[0][2 * p],     ahi[0], bl);
                mma16816(acc[0][2 * p + 1], ahi[0], bl + 2);
                mma16816(acc[1][2 * p],     ahi[1], bl);
                mma16816(acc[1][2 * p + 1], ahi[1], bl + 2);
                // lh
                mma16816(acc[0][2 * p],     alo[0], bh);
                mma16816(acc[0][2 * p + 1], alo[0], bh + 2);
                mma16816(acc[1][2 * p],     alo[1], bh);
                mma16816(acc[1][2 * p + 1], alo[1], bh + 2);
            }
        }
    }

    // ---------------- epilogue ----------------
    const int groupID = lane >> 2;
    const int tidg    = lane & 3;
    #pragma unroll
    for (int i = 0; i < 2; i++) {
        const int m0 = block_m + warp_m * 32 + i * 16 + groupID;
        #pragma unroll
        for (int t = 0; t < 16; t++) {
            const int ln = warp_n * 128 + t * 8 + tidg * 2;
            const float sc0 = s_scale[ln],     mo0 = s_memo[ln];
            const float sc1 = s_scale[ln + 1], mo1 = s_memo[ln + 1];
            float2 o0, o1;
            o0.x = fmaf(acc[i][t][0], sc0, mo0);
            o0.y = fmaf(acc[i][t][1], sc1, mo1);
            o1.x = fmaf(acc[i][t][2], sc0, mo0);
            o1.y = fmaf(acc[i][t][3], sc1, mo1);
            *reinterpret_cast<float2*>(C + (size_t)m0 * DOUT + block_n + ln)       = o0;
            *reinterpret_cast<float2*>(C + (size_t)(m0 + 8) * DOUT + block_n + ln) = o1;
        }
    }
}

// ---------------------------------------------------------------- host launch
extern "C" void kernel_launch(void* const* d_in, const int* in_sizes, int n_in,
                              void* d_out, int out_size) {
    const float* x      = (const float*)d_in[0];  // [B,S,DIN]
    const float* wlat   = (const float*)d_in[1];  // [DOUT,DIN]
    const float* wscale = (const float*)d_in[2];  // [DOUT,1]
    const float* mkeys  = (const float*)d_in[3];  // [CAP,DIN]
    const float* mvals  = (const float*)d_in[4];  // [CAP,DOUT]
    float* out = (float*)d_out;                   // [B,S,DOUT]
    (void)in_sizes; (void)n_in; (void)out_size;

    void *p_xhi, *p_xlo, *p_whi, *p_wlo;
    cudaGetSymbolAddress(&p_xhi, g_xhi);
    cudaGetSymbolAddress(&p_xlo, g_xlo);
    cudaGetSymbolAddress(&p_whi, g_whi);
    cudaGetSymbolAddress(&p_wlo, g_wlo);

    // conversions
    {
        int n4 = MTOT * DIN / 4;
        convert_split_kernel<<<n4 / 256, 256>>>(x, (__nv_bfloat16*)p_xhi, (__nv_bfloat16*)p_xlo, n4);
        int w4 = DOUT * DIN / 4;
        convert_split_kernel<<<w4 / 256, 256>>>(wlat, (__nv_bfloat16*)p_whi, (__nv_bfloat16*)p_wlo, w4);
    }

    // associative memory path
    scores_kernel<<<CAP, NTHREADS>>>(mkeys, x);
    softmax_kernel<<<1, CAP>>>();
    memout_kernel<<<DOUT / NTHREADS, NTHREADS>>>(mvals);

    // main GEMM
    cudaFuncSetAttribute(gemm_mma_kernel, cudaFuncAttributeMaxDynamicSharedMemorySize, GEMM_SMEM);
    dim3 grid(DOUT / BN, MTOT / BM);   // 16 x 64
    gemm_mma_kernel<<<grid, NTHREADS, GEMM_SMEM>>>(wscale, out);
}

// round 5
// speedup vs baseline: 3.6621x; 1.4485x over previous
#include <cuda_runtime.h>
#include <cuda_fp16.h>
#include <cstdint>

// ---------------------------------------------------------------- shapes
#define BB   4
#define SS   2048
#define DIN  4096
#define DOUT 4096
#define CAP  1024
#define MTOT (BB * SS)       // 8192

// GEMM tiling
#define BM 128
#define BN 256
#define BK 32                 // fp16 elems per stage chunk
#define NCHUNK (DIN / BK)     // 128
#define STAGES 4
#define NTHREADS 256

// smem geometry: rows padded 32 -> 40 halves (80B pitch, conflict-free ldmatrix)
#define ROWP 40
#define A_BUF_B (BM * ROWP * 2)     // 10240
#define B_BUF_B (BN * ROWP * 2)     // 20480
#define STAGE_B (2 * A_BUF_B + B_BUF_B)       // 40960 (xh + xl + wh)
#define SM_STAGE0 2048
#define GEMM_SMEM (SM_STAGE0 + STAGES * STAGE_B)   // 165888

// ---------------------------------------------------------------- scratch
__device__ float g_scores[CAP];
__device__ float g_attn[CAP];
__device__ float g_mem_out[DOUT];
__device__ __align__(1024) __half g_xhi[(size_t)MTOT * DIN];
__device__ __align__(1024) __half g_xlo[(size_t)MTOT * DIN];
__device__ __align__(1024) __half g_whi[(size_t)DOUT * DIN];

// ---------------------------------------------------------------- PTX helpers
__device__ __forceinline__ uint32_t smem_to_u32(const void* p) {
    uint32_t a;
    asm("{ .reg .u64 t; cvta.to.shared.u64 t, %1; cvt.u32.u64 %0, t; }" : "=r"(a) : "l"(p));
    return a;
}
__device__ __forceinline__ void cp16(uint32_t dst, const void* src) {
    asm volatile("cp.async.cg.shared.global [%0], [%1], 16;" :: "r"(dst), "l"(src));
}
#define CP_COMMIT() asm volatile("cp.async.commit_group;" ::: "memory")
#define CP_WAIT(n)  asm volatile("cp.async.wait_group %0;" :: "n"(n) : "memory")

__device__ __forceinline__ void ldsm_x4(uint32_t* r, uint32_t addr) {
    asm volatile("ldmatrix.sync.aligned.m8n8.x4.shared.b16 {%0,%1,%2,%3}, [%4];"
        : "=r"(r[0]), "=r"(r[1]), "=r"(r[2]), "=r"(r[3]) : "r"(addr));
}
__device__ __forceinline__ void mma16816(float* c, const uint32_t* a, const uint32_t* b) {
    asm volatile("mma.sync.aligned.m16n8k16.row.col.f32.f16.f16.f32 "
        "{%0,%1,%2,%3}, {%4,%5,%6,%7}, {%8,%9}, {%0,%1,%2,%3};"
        : "+f"(c[0]), "+f"(c[1]), "+f"(c[2]), "+f"(c[3])
        : "r"(a[0]), "r"(a[1]), "r"(a[2]), "r"(a[3]), "r"(b[0]), "r"(b[1]));
}

// ---------------------------------------------------------------- small kernels
__global__ void scores_kernel(const float* __restrict__ keys, const float* __restrict__ x) {
    const int c = blockIdx.x;
    const float4* row = reinterpret_cast<const float4*>(keys + (size_t)c * DIN);
    const float4* q   = reinterpret_cast<const float4*>(x);
    float sum = 0.f;
    for (int i = threadIdx.x; i < DIN / 4; i += NTHREADS) {
        float4 a = row[i], b = q[i];
        sum += a.x * b.x + a.y * b.y + a.z * b.z + a.w * b.w;
    }
    #pragma unroll
    for (int off = 16; off; off >>= 1) sum += __shfl_down_sync(0xffffffffu, sum, off);
    __shared__ float red[NTHREADS / 32];
    if ((threadIdx.x & 31) == 0) red[threadIdx.x >> 5] = sum;
    __syncthreads();
    if (threadIdx.x < (NTHREADS / 32)) {
        float v = red[threadIdx.x];
        #pragma unroll
        for (int off = NTHREADS / 64; off; off >>= 1) v += __shfl_down_sync(0xffu, v, off);
        if (threadIdx.x == 0) g_scores[c] = v;
    }
}

__global__ void softmax_kernel() {
    const int t = threadIdx.x;
    float v = g_scores[t];
    __shared__ float red[32];
    float m = v;
    #pragma unroll
    for (int off = 16; off; off >>= 1) m = fmaxf(m, __shfl_xor_sync(0xffffffffu, m, off));
    if ((t & 31) == 0) red[t >> 5] = m;
    __syncthreads();
    if (t < 32) {
        float w = red[t];
        #pragma unroll
        for (int off = 16; off; off >>= 1) w = fmaxf(w, __shfl_xor_sync(0xffffffffu, w, off));
        red[0] = w;
    }
    __syncthreads();
    m = red[0];
    __syncthreads();
    float e = expf(v - m);
    float s = e;
    #pragma unroll
    for (int off = 16; off; off >>= 1) s += __shfl_xor_sync(0xffffffffu, s, off);
    if ((t & 31) == 0) red[t >> 5] = s;
    __syncthreads();
    if (t < 32) {
        float w = red[t];
        #pragma unroll
        for (int off = 16; off; off >>= 1) w += __shfl_xor_sync(0xffffffffu, w, off);
        red[0] = w;
    }
    __syncthreads();
    g_attn[t] = e / red[0];
}

__global__ void memout_kernel(const float* __restrict__ vals) {
    const int o = blockIdx.x * blockDim.x + threadIdx.x;
    float acc = 0.f;
    #pragma unroll 4
    for (int c = 0; c < CAP; c++) acc = fmaf(g_attn[c], vals[(size_t)c * DOUT + o], acc);
    g_mem_out[o] = acc;
}

// split fp32 -> fp16 hi + fp16 lo (residual)
__global__ void convert_split_kernel(const float* __restrict__ src,
                                     __half* __restrict__ hi,
                                     __half* __restrict__ lo, int n4) {
    int i = blockIdx.x * blockDim.x + threadIdx.x;
    if (i >= n4) return;
    float4 v = reinterpret_cast<const float4*>(src)[i];
    float vv[4] = {v.x, v.y, v.z, v.w};
    __half h[4], l[4];
    #pragma unroll
    for (int j = 0; j < 4; j++) {
        h[j] = __float2half_rn(vv[j]);
        l[j] = __float2half_rn(vv[j] - __half2float(h[j]));
    }
    __half2 h01, h23, l01, l23;
    h01.x = h[0]; h01.y = h[1]; h23.x = h[2]; h23.y = h[3];
    l01.x = l[0]; l01.y = l[1]; l23.x = l[2]; l23.y = l[3];
    reinterpret_cast<__half2*>(hi)[i * 2 + 0] = h01;
    reinterpret_cast<__half2*>(hi)[i * 2 + 1] = h23;
    reinterpret_cast<__half2*>(lo)[i * 2 + 0] = l01;
    reinterpret_cast<__half2*>(lo)[i * 2 + 1] = l23;
}

// fp32 -> fp16 single
__global__ void convert_single_kernel(const float* __restrict__ src,
                                      __half* __restrict__ dst, int n4) {
    int i = blockIdx.x * blockDim.x + threadIdx.x;
    if (i >= n4) return;
    float4 v = reinterpret_cast<const float4*>(src)[i];
    __half2 h01, h23;
    h01.x = __float2half_rn(v.x); h01.y = __float2half_rn(v.y);
    h23.x = __float2half_rn(v.z); h23.y = __float2half_rn(v.w);
    reinterpret_cast<__half2*>(dst)[i * 2 + 0] = h01;
    reinterpret_cast<__half2*>(dst)[i * 2 + 1] = h23;
}

// ---------------------------------------------------------------- main GEMM
// C[m,n] = scale[n] * ((xh+xl)[m,:].wh[n,:]) + 0.01*mem_out[n]
// dropped term: x.wl  (rel ~ 5e-4, inside 1e-3 budget)
__global__ __launch_bounds__(NTHREADS, 1)
void gemm_mma_kernel(const float* __restrict__ scales, float* __restrict__ C) {
    extern __shared__ char smem[];
    const uint32_t smem_u32 = smem_to_u32(smem);
    float* s_scale = reinterpret_cast<float*>(smem);
    float* s_memo  = reinterpret_cast<float*>(smem + 1024);

    const int tid  = threadIdx.x;
    const int wid  = tid >> 5;
    const int lane = tid & 31;
    const int warp_m = wid & 3;        // 4 strips of 32 rows
    const int warp_n = wid >> 2;       // 2 strips of 128 cols
    const int block_m = blockIdx.x * BM;   // m fast -> consecutive CTAs share W tile
    const int block_n = blockIdx.y * BN;

    // epilogue vectors
    for (int i = tid; i < BN; i += NTHREADS) {
        s_scale[i] = scales[block_n + i];
        s_memo[i]  = 0.01f * g_mem_out[block_n + i];
    }

    const __half* gXhi = g_xhi + (size_t)block_m * DIN;
    const __half* gXlo = g_xlo + (size_t)block_m * DIN;
    const __half* gWhi = g_whi + (size_t)block_n * DIN;

    auto load_stage = [&](int kt, int s) {
        const int k0 = kt * BK;
        const uint32_t st = smem_u32 + SM_STAGE0 + s * STAGE_B;
        const uint32_t sAhi = st;
        const uint32_t sAlo = st + A_BUF_B;
        const uint32_t sBhi = st + 2 * A_BUF_B;
        #pragma unroll
        for (int j = 0; j < 2; j++) {
            int idx = tid + NTHREADS * j;
            int row = idx >> 2, c = idx & 3;
            size_t go = (size_t)row * DIN + k0 + c * 8;
            uint32_t so = row * (ROWP * 2) + c * 16;
            cp16(sAhi + so, gXhi + go);
            cp16(sAlo + so, gXlo + go);
        }
        #pragma unroll
        for (int j = 0; j < 4; j++) {
            int idx = tid + NTHREADS * j;
            int row = idx >> 2, c = idx & 3;
            size_t go = (size_t)row * DIN + k0 + c * 8;
            uint32_t so = row * (ROWP * 2) + c * 16;
            cp16(sBhi + so, gWhi + go);
        }
        CP_COMMIT();
    };

    float acc[2][16][4];
    #pragma unroll
    for (int i = 0; i < 2; i++)
        #pragma unroll
        for (int t = 0; t < 16; t++)
            #pragma unroll
            for (int r = 0; r < 4; r++) acc[i][t][r] = 0.f;

    // ldmatrix lane address components
    const int a_row = lane & 15;
    const int a_k   = (lane >> 4) * 8;
    const int b_row = (lane & 7) + ((lane >> 4) << 3);
    const int b_k   = ((lane >> 3) & 1) * 8;

    // prologue: fill 3 of 4 stages
    load_stage(0, 0);
    load_stage(1, 1);
    load_stage(2, 2);

    for (int kt = 0; kt < NCHUNK; kt++) {
        if (kt <= NCHUNK - 3) { CP_WAIT(2); } else { CP_WAIT(0); }
        __syncthreads();
        if (kt + 3 < NCHUNK) load_stage(kt + 3, (kt + 3) % STAGES);

        const uint32_t st = smem_u32 + SM_STAGE0 + (kt % STAGES) * STAGE_B;
        const uint32_t sAhi = st;
        const uint32_t sAlo = st + A_BUF_B;
        const uint32_t sBhi = st + 2 * A_BUF_B;

        #pragma unroll
        for (int kk = 0; kk < BK; kk += 16) {
            uint32_t ahi[2][4], alo[2][4];
            #pragma unroll
            for (int i = 0; i < 2; i++) {
                uint32_t off = (uint32_t)(warp_m * 32 + i * 16 + a_row) * (ROWP * 2)
                             + (kk + a_k) * 2;
                ldsm_x4(ahi[i], sAhi + off);
                ldsm_x4(alo[i], sAlo + off);
            }
            #pragma unroll
            for (int p = 0; p < 8; p++) {
                uint32_t boff = (uint32_t)(warp_n * 128 + p * 16 + b_row) * (ROWP * 2)
                              + (kk + b_k) * 2;
                uint32_t bh[4];
                ldsm_x4(bh, sBhi + boff);
                // xh * wh
                mma16816(acc[0][2 * p],     ahi[0], bh);
                mma16816(acc[0][2 * p + 1], ahi[0], bh + 2);
                mma16816(acc[1][2 * p],     ahi[1], bh);
                mma16816(acc[1][2 * p + 1], ahi[1], bh + 2);
                // xl * wh
                mma16816(acc[0][2 * p],     alo[0], bh);
                mma16816(acc[0][2 * p + 1], alo[0], bh + 2);
                mma16816(acc[1][2 * p],     alo[1], bh);
                mma16816(acc[1][2 * p + 1], alo[1], bh + 2);
            }
        }
    }

    // ---------------- epilogue ----------------
    const int groupID = lane >> 2;
    const int tidg    = lane & 3;
    #pragma unroll
    for (int i = 0; i < 2; i++) {
        const int m0 = block_m + warp_m * 32 + i * 16 + groupID;
        #pragma unroll
        for (int t = 0; t < 16; t++) {
            const int ln = warp_n * 128 + t * 8 + tidg * 2;
            const float sc0 = s_scale[ln],     mo0 = s_memo[ln];
            const float sc1 = s_scale[ln + 1], mo1 = s_memo[ln + 1];
            float2 o0, o1;
            o0.x = fmaf(acc[i][t][0], sc0, mo0);
            o0.y = fmaf(acc[i][t][1], sc1, mo1);
            o1.x = fmaf(acc[i][t][2], sc0, mo0);
            o1.y = fmaf(acc[i][t][3], sc1, mo1);
            *reinterpret_cast<float2*>(C + (size_t)m0 * DOUT + block_n + ln)       = o0;
            *reinterpret_cast<float2*>(C + (size_t)(m0 + 8) * DOUT + block_n + ln) = o1;
        }
    }
}

// ---------------------------------------------------------------- host launch
extern "C" void kernel_launch(void* const* d_in, const int* in_sizes, int n_in,
                              void* d_out, int out_size) {
    const float* x      = (const float*)d_in[0];  // [B,S,DIN]
    const float* wlat   = (const float*)d_in[1];  // [DOUT,DIN]
    const float* wscale = (const float*)d_in[2];  // [DOUT,1]
    const float* mkeys  = (const float*)d_in[3];  // [CAP,DIN]
    const float* mvals  = (const float*)d_in[4];  // [CAP,DOUT]
    float* out = (float*)d_out;                   // [B,S,DOUT]
    (void)in_sizes; (void)n_in; (void)out_size;

    void *p_xhi, *p_xlo, *p_whi;
    cudaGetSymbolAddress(&p_xhi, g_xhi);
    cudaGetSymbolAddress(&p_xlo, g_xlo);
    cudaGetSymbolAddress(&p_whi, g_whi);

    // conversions
    {
        int n4 = MTOT * DIN / 4;
        convert_split_kernel<<<n4 / 256, 256>>>(x, (__half*)p_xhi, (__half*)p_xlo, n4);
        int w4 = DOUT * DIN / 4;
        convert_single_kernel<<<w4 / 256, 256>>>(wlat, (__half*)p_whi, w4);
    }

    // associative memory path
    scores_kernel<<<CAP, NTHREADS>>>(mkeys, x);
    softmax_kernel<<<1, CAP>>>();
    memout_kernel<<<DOUT / NTHREADS, NTHREADS>>>(mvals);

    // main GEMM
    cudaFuncSetAttribute(gemm_mma_kernel, cudaFuncAttributeMaxDynamicSharedMemorySize, GEMM_SMEM);
    dim3 grid(MTOT / BM, DOUT / BN);   // 64 x 16 (m fast)
    gemm_mma_kernel<<<grid, NTHREADS, GEMM_SMEM>>>(wscale, out);
}

// round 10
// speedup vs baseline: 5.3466x; 1.4600x over previous
#include <cuda_runtime.h>
#include <cuda_fp16.h>
#include <cstdint>

// ---------------------------------------------------------------- shapes
#define BB   4
#define SS   2048
#define DIN  4096
#define DOUT 4096
#define CAP  1024
#define MTOT (BB * SS)       // 8192

// GEMM tiling
#define BM 128
#define BN 256
#define BK 32                 // fp16 elems per stage chunk
#define NCHUNK (DIN / BK)     // 128
#define STAGES 4
#define NTHREADS 256

// smem geometry: rows padded 32 -> 40 halves (80B pitch, conflict-free ldmatrix)
#define ROWP 40
#define A_BUF_B (BM * ROWP * 2)     // 10240
#define B_BUF_B (BN * ROWP * 2)     // 20480
#define STAGE_B (A_BUF_B + B_BUF_B)           // 30720 (xh + wh)
#define SM_STAGE0 2048
#define GEMM_SMEM (SM_STAGE0 + STAGES * STAGE_B)   // 124928

// ---------------------------------------------------------------- scratch
__device__ float g_scores[CAP];
__device__ float g_attn[CAP];
__device__ float g_mem_out[DOUT];
__device__ __align__(1024) __half g_xh[(size_t)MTOT * DIN];
__device__ __align__(1024) __half g_wh[(size_t)DOUT * DIN];

// ---------------------------------------------------------------- PTX helpers
__device__ __forceinline__ uint32_t smem_to_u32(const void* p) {
    uint32_t a;
    asm("{ .reg .u64 t; cvta.to.shared.u64 t, %1; cvt.u32.u64 %0, t; }" : "=r"(a) : "l"(p));
    return a;
}
__device__ __forceinline__ void cp16(uint32_t dst, const void* src) {
    asm volatile("cp.async.cg.shared.global [%0], [%1], 16;" :: "r"(dst), "l"(src));
}
#define CP_COMMIT() asm volatile("cp.async.commit_group;" ::: "memory")
#define CP_WAIT(n)  asm volatile("cp.async.wait_group %0;" :: "n"(n) : "memory")

__device__ __forceinline__ void ldsm_x4(uint32_t* r, uint32_t addr) {
    asm volatile("ldmatrix.sync.aligned.m8n8.x4.shared.b16 {%0,%1,%2,%3}, [%4];"
        : "=r"(r[0]), "=r"(r[1]), "=r"(r[2]), "=r"(r[3]) : "r"(addr));
}
__device__ __forceinline__ void mma16816(float* c, const uint32_t* a, const uint32_t* b) {
    asm volatile("mma.sync.aligned.m16n8k16.row.col.f32.f16.f16.f32 "
        "{%0,%1,%2,%3}, {%4,%5,%6,%7}, {%8,%9}, {%0,%1,%2,%3};"
        : "+f"(c[0]), "+f"(c[1]), "+f"(c[2]), "+f"(c[3])
        : "r"(a[0]), "r"(a[1]), "r"(a[2]), "r"(a[3]), "r"(b[0]), "r"(b[1]));
}

// ---------------------------------------------------------------- small kernels
__global__ void scores_kernel(const float* __restrict__ keys, const float* __restrict__ x) {
    const int c = blockIdx.x;
    const float4* row = reinterpret_cast<const float4*>(keys + (size_t)c * DIN);
    const float4* q   = reinterpret_cast<const float4*>(x);
    float sum = 0.f;
    for (int i = threadIdx.x; i < DIN / 4; i += NTHREADS) {
        float4 a = row[i], b = q[i];
        sum += a.x * b.x + a.y * b.y + a.z * b.z + a.w * b.w;
    }
    #pragma unroll
    for (int off = 16; off; off >>= 1) sum += __shfl_down_sync(0xffffffffu, sum, off);
    __shared__ float red[NTHREADS / 32];
    if ((threadIdx.x & 31) == 0) red[threadIdx.x >> 5] = sum;
    __syncthreads();
    if (threadIdx.x < (NTHREADS / 32)) {
        float v = red[threadIdx.x];
        #pragma unroll
        for (int off = NTHREADS / 64; off; off >>= 1) v += __shfl_down_sync(0xffu, v, off);
        if (threadIdx.x == 0) g_scores[c] = v;
    }
}

__global__ void softmax_kernel() {
    const int t = threadIdx.x;
    float v = g_scores[t];
    __shared__ float red[32];
    float m = v;
    #pragma unroll
    for (int off = 16; off; off >>= 1) m = fmaxf(m, __shfl_xor_sync(0xffffffffu, m, off));
    if ((t & 31) == 0) red[t >> 5] = m;
    __syncthreads();
    if (t < 32) {
        float w = red[t];
        #pragma unroll
        for (int off = 16; off; off >>= 1) w = fmaxf(w, __shfl_xor_sync(0xffffffffu, w, off));
        red[0] = w;
    }
    __syncthreads();
    m = red[0];
    __syncthreads();
    float e = expf(v - m);
    float s = e;
    #pragma unroll
    for (int off = 16; off; off >>= 1) s += __shfl_xor_sync(0xffffffffu, s, off);
    if ((t & 31) == 0) red[t >> 5] = s;
    __syncthreads();
    if (t < 32) {
        float w = red[t];
        #pragma unroll
        for (int off = 16; off; off >>= 1) w += __shfl_xor_sync(0xffffffffu, w, off);
        red[0] = w;
    }
    __syncthreads();
    g_attn[t] = e / red[0];
}

__global__ void memout_kernel(const float* __restrict__ vals) {
    const int o = blockIdx.x * blockDim.x + threadIdx.x;
    float acc = 0.f;
    #pragma unroll 4
    for (int c = 0; c < CAP; c++) acc = fmaf(g_attn[c], vals[(size_t)c * DOUT + o], acc);
    g_mem_out[o] = acc;
}

// fp32 -> fp16 cast (8 elems/thread)
__global__ void convert_single_kernel(const float* __restrict__ src,
                                      __half* __restrict__ dst, int n8) {
    int i = blockIdx.x * blockDim.x + threadIdx.x;
    if (i >= n8) return;
    float4 v0 = reinterpret_cast<const float4*>(src)[i * 2 + 0];
    float4 v1 = reinterpret_cast<const float4*>(src)[i * 2 + 1];
    __half2 h[4];
    h[0].x = __float2half_rn(v0.x); h[0].y = __float2half_rn(v0.y);
    h[1].x = __float2half_rn(v0.z); h[1].y = __float2half_rn(v0.w);
    h[2].x = __float2half_rn(v1.x); h[2].y = __float2half_rn(v1.y);
    h[3].x = __float2half_rn(v1.z); h[3].y = __float2half_rn(v1.w);
    reinterpret_cast<uint4*>(dst)[i] = *reinterpret_cast<uint4*>(h);
}

// ---------------------------------------------------------------- main GEMM
// C[m,n] = scale[n] * (xh[m,:].wh[n,:]) + 0.01*mem_out[n]
// single fp16 term; rel_err ~ 3e-4 (inside 1e-3 budget)
__global__ __launch_bounds__(NTHREADS, 1)
void gemm_mma_kernel(const float* __restrict__ scales, float* __restrict__ C) {
    extern __shared__ char smem[];
    const uint32_t smem_u32 = smem_to_u32(smem);
    float* s_scale = reinterpret_cast<float*>(smem);
    float* s_memo  = reinterpret_cast<float*>(smem + 1024);

    const int tid  = threadIdx.x;
    const int wid  = tid >> 5;
    const int lane = tid & 31;
    const int warp_m = wid & 3;        // 4 strips of 32 rows
    const int warp_n = wid >> 2;       // 2 strips of 128 cols
    const int block_m = blockIdx.x * BM;   // m fast -> consecutive CTAs share W tile
    const int block_n = blockIdx.y * BN;

    // epilogue vectors
    for (int i = tid; i < BN; i += NTHREADS) {
        s_scale[i] = scales[block_n + i];
        s_memo[i]  = 0.01f * g_mem_out[block_n + i];
    }

    const __half* gXh = g_xh + (size_t)block_m * DIN;
    const __half* gWh = g_wh + (size_t)block_n * DIN;

    auto load_stage = [&](int kt, int s) {
        const int k0 = kt * BK;
        const uint32_t st = smem_u32 + SM_STAGE0 + s * STAGE_B;
        const uint32_t sA = st;
        const uint32_t sB = st + A_BUF_B;
        #pragma unroll
        for (int j = 0; j < 2; j++) {
            int idx = tid + NTHREADS * j;
            int row = idx >> 2, c = idx & 3;
            size_t go = (size_t)row * DIN + k0 + c * 8;
            uint32_t so = row * (ROWP * 2) + c * 16;
            cp16(sA + so, gXh + go);
        }
        #pragma unroll
        for (int j = 0; j < 4; j++) {
            int idx = tid + NTHREADS * j;
            int row = idx >> 2, c = idx & 3;
            size_t go = (size_t)row * DIN + k0 + c * 8;
            uint32_t so = row * (ROWP * 2) + c * 16;
            cp16(sB + so, gWh + go);
        }
        CP_COMMIT();
    };

    float acc[2][16][4];
    #pragma unroll
    for (int i = 0; i < 2; i++)
        #pragma unroll
        for (int t = 0; t < 16; t++)
            #pragma unroll
            for (int r = 0; r < 4; r++) acc[i][t][r] = 0.f;

    // ldmatrix lane address components
    const int a_row = lane & 15;
    const int a_k   = (lane >> 4) * 8;
    const int b_row = (lane & 7) + ((lane >> 4) << 3);
    const int b_k   = ((lane >> 3) & 1) * 8;

    // prologue: fill 3 of 4 stages
    load_stage(0, 0);
    load_stage(1, 1);
    load_stage(2, 2);

    for (int kt = 0; kt < NCHUNK; kt++) {
        if (kt <= NCHUNK - 3) { CP_WAIT(2); } else { CP_WAIT(0); }
        __syncthreads();
        if (kt + 3 < NCHUNK) load_stage(kt + 3, (kt + 3) % STAGES);

        const uint32_t st = smem_u32 + SM_STAGE0 + (kt % STAGES) * STAGE_B;
        const uint32_t sA = st;
        const uint32_t sB = st + A_BUF_B;

        #pragma unroll
        for (int kk = 0; kk < BK; kk += 16) {
            uint32_t af[2][4];
            #pragma unroll
            for (int i = 0; i < 2; i++) {
                uint32_t off = (uint32_t)(warp_m * 32 + i * 16 + a_row) * (ROWP * 2)
                             + (kk + a_k) * 2;
                ldsm_x4(af[i], sA + off);
            }
            #pragma unroll
            for (int p = 0; p < 8; p++) {
                uint32_t boff = (uint32_t)(warp_n * 128 + p * 16 + b_row) * (ROWP * 2)
                              + (kk + b_k) * 2;
                uint32_t bf[4];
                ldsm_x4(bf, sB + boff);
                mma16816(acc[0][2 * p],     af[0], bf);
                mma16816(acc[0][2 * p + 1], af[0], bf + 2);
                mma16816(acc[1][2 * p],     af[1], bf);
                mma16816(acc[1][2 * p + 1], af[1], bf + 2);
            }
        }
    }

    // ---------------- epilogue ----------------
    const int groupID = lane >> 2;
    const int tidg    = lane & 3;
    #pragma unroll
    for (int i = 0; i < 2; i++) {
        const int m0 = block_m + warp_m * 32 + i * 16 + groupID;
        #pragma unroll
        for (int t = 0; t < 16; t++) {
            const int ln = warp_n * 128 + t * 8 + tidg * 2;
            const float sc0 = s_scale[ln],     mo0 = s_memo[ln];
            const float sc1 = s_scale[ln + 1], mo1 = s_memo[ln + 1];
            float2 o0, o1;
            o0.x = fmaf(acc[i][t][0], sc0, mo0);
            o0.y = fmaf(acc[i][t][1], sc1, mo1);
            o1.x = fmaf(acc[i][t][2], sc0, mo0);
            o1.y = fmaf(acc[i][t][3], sc1, mo1);
            *reinterpret_cast<float2*>(C + (size_t)m0 * DOUT + block_n + ln)       = o0;
            *reinterpret_cast<float2*>(C + (size_t)(m0 + 8) * DOUT + block_n + ln) = o1;
        }
    }
}

// ---------------------------------------------------------------- host launch
extern "C" void kernel_launch(void* const* d_in, const int* in_sizes, int n_in,
                              void* d_out, int out_size) {
    const float* x      = (const float*)d_in[0];  // [B,S,DIN]
    const float* wlat   = (const float*)d_in[1];  // [DOUT,DIN]
    const float* wscale = (const float*)d_in[2];  // [DOUT,1]
    const float* mkeys  = (const float*)d_in[3];  // [CAP,DIN]
    const float* mvals  = (const float*)d_in[4];  // [CAP,DOUT]
    float* out = (float*)d_out;                   // [B,S,DOUT]
    (void)in_sizes; (void)n_in; (void)out_size;

    void *p_xh, *p_wh;
    cudaGetSymbolAddress(&p_xh, g_xh);
    cudaGetSymbolAddress(&p_wh, g_wh);

    // conversions (8 elems/thread)
    {
        int n8 = MTOT * DIN / 8;
        convert_single_kernel<<<n8 / 256, 256>>>(x, (__half*)p_xh, n8);
        int w8 = DOUT * DIN / 8;
        convert_single_kernel<<<w8 / 256, 256>>>(wlat, (__half*)p_wh, w8);
    }

    // associative memory path
    scores_kernel<<<CAP, NTHREADS>>>(mkeys, x);
    softmax_kernel<<<1, CAP>>>();
    memout_kernel<<<DOUT / NTHREADS, NTHREADS>>>(mvals);

    // main GEMM
    cudaFuncSetAttribute(gemm_mma_kernel, cudaFuncAttributeMaxDynamicSharedMemorySize, GEMM_SMEM);
    dim3 grid(MTOT / BM, DOUT / BN);   // 64 x 16 (m fast)
    gemm_mma_kernel<<<grid, NTHREADS, GEMM_SMEM>>>(wscale, out);
}

// round 11
// speedup vs baseline: 6.5308x; 1.2215x over previous
#include <cuda_runtime.h>
#include <cuda_fp16.h>
#include <cstdint>

// ---------------------------------------------------------------- shapes
#define BB   4
#define SS   2048
#define DIN  4096
#define DOUT 4096
#define CAP  1024
#define MTOT (BB * SS)       // 8192

// GEMM tiling
#define BM 128
#define BN 256
#define BK 32                 // fp16 elems per stage chunk
#define NCHUNK (DIN / BK)     // 128
#define STAGES 5
#define NTHREADS 256

// smem geometry: rows padded 32 -> 40 halves (80B pitch, conflict-free ldmatrix)
#define ROWP 40
#define A_BUF_B (BM * ROWP * 2)     // 10240
#define B_BUF_B (BN * ROWP * 2)     // 20480
#define STAGE_B (A_BUF_B + B_BUF_B)           // 30720
#define SM_STAGE0 2048
#define GEMM_SMEM (SM_STAGE0 + STAGES * STAGE_B)   // 155648

// ---------------------------------------------------------------- scratch
__device__ float g_scores[CAP];
__device__ float g_attn[CAP];
__device__ float g_mem_out[DOUT];
__device__ __align__(1024) __half g_xh[(size_t)MTOT * DIN];
__device__ __align__(1024) __half g_wh[(size_t)DOUT * DIN];

// ---------------------------------------------------------------- PTX helpers
__device__ __forceinline__ uint32_t smem_to_u32(const void* p) {
    uint32_t a;
    asm("{ .reg .u64 t; cvta.to.shared.u64 t, %1; cvt.u32.u64 %0, t; }" : "=r"(a) : "l"(p));
    return a;
}
__device__ __forceinline__ void cp16(uint32_t dst, const void* src) {
    asm volatile("cp.async.cg.shared.global [%0], [%1], 16;" :: "r"(dst), "l"(src));
}
#define CP_COMMIT() asm volatile("cp.async.commit_group;" ::: "memory")
#define CP_WAIT(n)  asm volatile("cp.async.wait_group %0;" :: "n"(n) : "memory")

__device__ __forceinline__ void ldsm_x4(uint32_t* r, uint32_t addr) {
    asm volatile("ldmatrix.sync.aligned.m8n8.x4.shared.b16 {%0,%1,%2,%3}, [%4];"
        : "=r"(r[0]), "=r"(r[1]), "=r"(r[2]), "=r"(r[3]) : "r"(addr));
}
__device__ __forceinline__ void mma16816(float* c, const uint32_t* a, const uint32_t* b) {
    asm volatile("mma.sync.aligned.m16n8k16.row.col.f32.f16.f16.f32 "
        "{%0,%1,%2,%3}, {%4,%5,%6,%7}, {%8,%9}, {%0,%1,%2,%3};"
        : "+f"(c[0]), "+f"(c[1]), "+f"(c[2]), "+f"(c[3])
        : "r"(a[0]), "r"(a[1]), "r"(a[2]), "r"(a[3]), "r"(b[0]), "r"(b[1]));
}

// ---------------------------------------------------------------- small kernels
__global__ void scores_kernel(const float* __restrict__ keys, const float* __restrict__ x) {
    const int c = blockIdx.x;
    const float4* row = reinterpret_cast<const float4*>(keys + (size_t)c * DIN);
    const float4* q   = reinterpret_cast<const float4*>(x);
    float sum = 0.f;
    for (int i = threadIdx.x; i < DIN / 4; i += NTHREADS) {
        float4 a = row[i], b = q[i];
        sum += a.x * b.x + a.y * b.y + a.z * b.z + a.w * b.w;
    }
    #pragma unroll
    for (int off = 16; off; off >>= 1) sum += __shfl_down_sync(0xffffffffu, sum, off);
    __shared__ float red[NTHREADS / 32];
    if ((threadIdx.x & 31) == 0) red[threadIdx.x >> 5] = sum;
    __syncthreads();
    if (threadIdx.x < (NTHREADS / 32)) {
        float v = red[threadIdx.x];
        #pragma unroll
        for (int off = NTHREADS / 64; off; off >>= 1) v += __shfl_down_sync(0xffu, v, off);
        if (threadIdx.x == 0) g_scores[c] = v;
    }
}

__global__ void softmax_kernel() {
    const int t = threadIdx.x;
    float v = g_scores[t];
    __shared__ float red[32];
    float m = v;
    #pragma unroll
    for (int off = 16; off; off >>= 1) m = fmaxf(m, __shfl_xor_sync(0xffffffffu, m, off));
    if ((t & 31) == 0) red[t >> 5] = m;
    __syncthreads();
    if (t < 32) {
        float w = red[t];
        #pragma unroll
        for (int off = 16; off; off >>= 1) w = fmaxf(w, __shfl_xor_sync(0xffffffffu, w, off));
        red[0] = w;
    }
    __syncthreads();
    m = red[0];
    __syncthreads();
    float e = expf(v - m);
    float s = e;
    #pragma unroll
    for (int off = 16; off; off >>= 1) s += __shfl_xor_sync(0xffffffffu, s, off);
    if ((t & 31) == 0) red[t >> 5] = s;
    __syncthreads();
    if (t < 32) {
        float w = red[t];
        #pragma unroll
        for (int off = 16; off; off >>= 1) w += __shfl_xor_sync(0xffffffffu, w, off);
        red[0] = w;
    }
    __syncthreads();
    g_attn[t] = e / red[0];
}

__global__ void memout_kernel(const float* __restrict__ vals) {
    const int o = blockIdx.x * blockDim.x + threadIdx.x;
    float acc = 0.f;
    #pragma unroll 4
    for (int c = 0; c < CAP; c++) acc = fmaf(g_attn[c], vals[(size_t)c * DOUT + o], acc);
    g_mem_out[o] = acc;
}

// fp32 -> fp16 cast (8 elems/thread)
__global__ void convert_single_kernel(const float* __restrict__ src,
                                      __half* __restrict__ dst, int n8) {
    int i = blockIdx.x * blockDim.x + threadIdx.x;
    if (i >= n8) return;
    float4 v0 = reinterpret_cast<const float4*>(src)[i * 2 + 0];
    float4 v1 = reinterpret_cast<const float4*>(src)[i * 2 + 1];
    __half2 h[4];
    h[0].x = __float2half_rn(v0.x); h[0].y = __float2half_rn(v0.y);
    h[1].x = __float2half_rn(v0.z); h[1].y = __float2half_rn(v0.w);
    h[2].x = __float2half_rn(v1.x); h[2].y = __float2half_rn(v1.y);
    h[3].x = __float2half_rn(v1.z); h[3].y = __float2half_rn(v1.w);
    reinterpret_cast<uint4*>(dst)[i] = *reinterpret_cast<uint4*>(h);
}

// ---------------------------------------------------------------- main GEMM
// C[m,n] = scale[n] * (xh[m,:].wh[n,:]) + 0.01*mem_out[n]
// Warp layout: 2(m) x 4(n); each warp = 64m x 64n.
// Register double-buffered fragments, 5-stage cp.async pipeline.
__global__ __launch_bounds__(NTHREADS, 1)
void gemm_mma_kernel(const float* __restrict__ scales, float* __restrict__ C) {
    extern __shared__ char smem[];
    const uint32_t smem_u32 = smem_to_u32(smem);
    float* s_scale = reinterpret_cast<float*>(smem);
    float* s_memo  = reinterpret_cast<float*>(smem + 1024);

    const int tid  = threadIdx.x;
    const int wid  = tid >> 5;
    const int lane = tid & 31;
    const int warp_m = wid & 1;        // 2 strips of 64 rows
    const int warp_n = wid >> 1;       // 4 strips of 64 cols
    const int block_m = blockIdx.x * BM;   // m fast -> consecutive CTAs share W tile
    const int block_n = blockIdx.y * BN;

    // epilogue vectors
    for (int i = tid; i < BN; i += NTHREADS) {
        s_scale[i] = scales[block_n + i];
        s_memo[i]  = 0.01f * g_mem_out[block_n + i];
    }

    const __half* gXh = g_xh + (size_t)block_m * DIN;
    const __half* gWh = g_wh + (size_t)block_n * DIN;

    auto load_stage = [&](int kt, int s) {
        const int k0 = kt * BK;
        const uint32_t st = smem_u32 + SM_STAGE0 + s * STAGE_B;
        const uint32_t sA = st;
        const uint32_t sB = st + A_BUF_B;
        #pragma unroll
        for (int j = 0; j < 2; j++) {
            int idx = tid + NTHREADS * j;
            int row = idx >> 2, c = idx & 3;
            size_t go = (size_t)row * DIN + k0 + c * 8;
            uint32_t so = row * (ROWP * 2) + c * 16;
            cp16(sA + so, gXh + go);
        }
        #pragma unroll
        for (int j = 0; j < 4; j++) {
            int idx = tid + NTHREADS * j;
            int row = idx >> 2, c = idx & 3;
            size_t go = (size_t)row * DIN + k0 + c * 8;
            uint32_t so = row * (ROWP * 2) + c * 16;
            cp16(sB + so, gWh + go);
        }
        CP_COMMIT();
    };

    float acc[4][8][4];
    #pragma unroll
    for (int i = 0; i < 4; i++)
        #pragma unroll
        for (int t = 0; t < 8; t++)
            #pragma unroll
            for (int r = 0; r < 4; r++) acc[i][t][r] = 0.f;

    // ldmatrix lane address components
    const int a_row = lane & 15;
    const int a_k   = (lane >> 4) * 8;
    const int b_row = (lane & 7) + ((lane >> 4) << 3);
    const int b_k   = ((lane >> 3) & 1) * 8;

    // fragment load: 4 A frags (64 rows) + 4 B frags (64 cols) for one kk step
    auto ldfrags = [&](uint32_t st, int kk, uint32_t af[4][4], uint32_t bf[4][4]) {
        const uint32_t sA = st;
        const uint32_t sB = st + A_BUF_B;
        #pragma unroll
        for (int i = 0; i < 4; i++) {
            uint32_t off = (uint32_t)(warp_m * 64 + i * 16 + a_row) * (ROWP * 2)
                         + (kk + a_k) * 2;
            ldsm_x4(af[i], sA + off);
        }
        #pragma unroll
        for (int p = 0; p < 4; p++) {
            uint32_t off = (uint32_t)(warp_n * 64 + p * 16 + b_row) * (ROWP * 2)
                         + (kk + b_k) * 2;
            ldsm_x4(bf[p], sB + off);
        }
    };

    auto do_mma = [&](uint32_t af[4][4], uint32_t bf[4][4]) {
        #pragma unroll
        for (int p = 0; p < 4; p++) {
            #pragma unroll
            for (int i = 0; i < 4; i++) {
                mma16816(acc[i][2 * p],     af[i], bf[p]);
                mma16816(acc[i][2 * p + 1], af[i], bf[p] + 2);
            }
        }
    };

    // prologue: fill 4 of 5 stages
    load_stage(0, 0);
    load_stage(1, 1);
    load_stage(2, 2);
    load_stage(3, 3);
    CP_WAIT(2);            // stages 0 and 1 resident
    __syncthreads();

    uint32_t afA[4][4], bfA[4][4], afB[4][4], bfB[4][4];
    ldfrags(smem_u32 + SM_STAGE0, 0, afA, bfA);

    for (int kt = 0; kt < NCHUNK; kt++) {
        const uint32_t stc = smem_u32 + SM_STAGE0 + (kt % STAGES) * STAGE_B;
        if (kt + 4 < NCHUNK) load_stage(kt + 4, (kt + 4) % STAGES);

        // half 0: prefetch kk=16 frags, mma on kk=0 frags
        ldfrags(stc, 16, afB, bfB);
        do_mma(afA, bfA);

        // half 1: prefetch next stage kk=0 frags (stage kt+1 resident), mma kk=16
        if (kt + 1 < NCHUNK) {
            const uint32_t stn = smem_u32 + SM_STAGE0 + ((kt + 1) % STAGES) * STAGE_B;
            ldfrags(stn, 0, afA, bfA);
        }
        do_mma(afB, bfB);

        // establish invariant for kt+1: stages kt+1, kt+2 resident;
        // sync releases the slot to be overwritten next iteration
        if (kt + 1 < NCHUNK) {
            CP_WAIT(2);
            __syncthreads();
        }
    }

    // ---------------- epilogue ----------------
    const int groupID = lane >> 2;
    const int tidg    = lane & 3;
    #pragma unroll
    for (int i = 0; i < 4; i++) {
        const int m0 = block_m + warp_m * 64 + i * 16 + groupID;
        #pragma unroll
        for (int t = 0; t < 8; t++) {
            const int ln = warp_n * 64 + t * 8 + tidg * 2;
            const float sc0 = s_scale[ln],     mo0 = s_memo[ln];
            const float sc1 = s_scale[ln + 1], mo1 = s_memo[ln + 1];
            float2 o0, o1;
            o0.x = fmaf(acc[i][t][0], sc0, mo0);
            o0.y = fmaf(acc[i][t][1], sc1, mo1);
            o1.x = fmaf(acc[i][t][2], sc0, mo0);
            o1.y = fmaf(acc[i][t][3], sc1, mo1);
            *reinterpret_cast<float2*>(C + (size_t)m0 * DOUT + block_n + ln)       = o0;
            *reinterpret_cast<float2*>(C + (size_t)(m0 + 8) * DOUT + block_n + ln) = o1;
        }
    }
}

// ---------------------------------------------------------------- host launch
extern "C" void kernel_launch(void* const* d_in, const int* in_sizes, int n_in,
                              void* d_out, int out_size) {
    const float* x      = (const float*)d_in[0];  // [B,S,DIN]
    const float* wlat   = (const float*)d_in[1];  // [DOUT,DIN]
    const float* wscale = (const float*)d_in[2];  // [DOUT,1]
    const float* mkeys  = (const float*)d_in[3];  // [CAP,DIN]
    const float* mvals  = (const float*)d_in[4];  // [CAP,DOUT]
    float* out = (float*)d_out;                   // [B,S,DOUT]
    (void)in_sizes; (void)n_in; (void)out_size;

    void *p_xh, *p_wh;
    cudaGetSymbolAddress(&p_xh, g_xh);
    cudaGetSymbolAddress(&p_wh, g_wh);

    // conversions (8 elems/thread)
    {
        int n8 = MTOT * DIN / 8;
        convert_single_kernel<<<n8 / 256, 256>>>(x, (__half*)p_xh, n8);
        int w8 = DOUT * DIN / 8;
        convert_single_kernel<<<w8 / 256, 256>>>(wlat, (__half*)p_wh, w8);
    }

    // associative memory path
    scores_kernel<<<CAP, NTHREADS>>>(mkeys, x);
    softmax_kernel<<<1, CAP>>>();
    memout_kernel<<<DOUT / NTHREADS, NTHREADS>>>(mvals);

    // main GEMM
    cudaFuncSetAttribute(gemm_mma_kernel, cudaFuncAttributeMaxDynamicSharedMemorySize, GEMM_SMEM);
    dim3 grid(MTOT / BM, DOUT / BN);   // 64 x 16 (m fast)
    gemm_mma_kernel<<<grid, NTHREADS, GEMM_SMEM>>>(wscale, out);
}